// round 2
// baseline (speedup 1.0000x reference)
#include <cuda_runtime.h>
#include <math.h>

#define Bsz 512
#define Tsz 512
#define Dsz 256

// out = [p (512) | T_event (512x513) | L_t (512x256) | M_t (512)]
#define OFF_TE 512
#define OFF_L  (512 + 512*513)
#define OFF_M  (OFF_L + 512*256)

__device__ __align__(16) float g_G[Dsz*Dsz];   // G[d1,d2] = sum_e WQ[e,d1]*WK[e,d2]

// ---------------- Kernel 0: G = W_Q^T @ W_K (tiny) ----------------
__global__ void k_G(const float* __restrict__ WQ, const float* __restrict__ WK) {
    int d1b = blockIdx.x * 4, d2 = threadIdx.x;
    float a0 = 0.f, a1 = 0.f, a2 = 0.f, a3 = 0.f;
    #pragma unroll 4
    for (int e = 0; e < Dsz; e++) {
        float wk = __ldg(WK + e*Dsz + d2);
        a0 = fmaf(__ldg(WQ + e*Dsz + d1b + 0), wk, a0);
        a1 = fmaf(__ldg(WQ + e*Dsz + d1b + 1), wk, a1);
        a2 = fmaf(__ldg(WQ + e*Dsz + d1b + 2), wk, a2);
        a3 = fmaf(__ldg(WQ + e*Dsz + d1b + 3), wk, a3);
    }
    g_G[(d1b+0)*Dsz + d2] = a0;
    g_G[(d1b+1)*Dsz + d2] = a1;
    g_G[(d1b+2)*Dsz + d2] = a2;
    g_G[(d1b+3)*Dsz + d2] = a3;
}

// ---------------- Fused main kernel: one CTA per batch row ----------------
__global__ void __launch_bounds__(512, 1)
k_main(const float* __restrict__ wf, const float* __restrict__ ts,
       const unsigned char* __restrict__ pad,
       const float* __restrict__ WV, const float* __restrict__ prevL,
       const float* __restrict__ prevM, const float* __restrict__ clsw,
       const float* __restrict__ clsb, float* __restrict__ out) {
    int b = blockIdx.x;
    int tid = threadIdx.x;
    int warp = tid >> 5, lane = tid & 31;

    __shared__ float s_lam[Tsz];
    __shared__ float s_valid[Tsz];
    __shared__ float s_q[Dsz];
    __shared__ float s_u[Dsz];
    __shared__ float s_yf[Dsz];
    __shared__ float s_L[Dsz];
    __shared__ float s_red[512];
    __shared__ float s_red2[512];
    __shared__ __align__(16) float s_acc[8*Dsz];    // pass-A partials (8 groups x 256)
    __shared__ __align__(16) float s_yp[16*Dsz];    // pass-B warp partials
    __shared__ float s_m[16], s_Z[16], s_S[16];

    // ---- step 1: valid mask, t_max, count, stash ts ----
    {
        float v = pad[b*Tsz + tid] ? 0.f : 1.f;
        s_valid[tid] = v;
        float tv = ts[b*Tsz + tid];
        s_lam[tid] = tv;                        // stash raw timestamp
        s_red[tid]  = (v > 0.f) ? tv : -3.0e38f;
        s_red2[tid] = v;
    }
    __syncthreads();
    for (int s = 256; s > 0; s >>= 1) {
        if (tid < s) {
            s_red[tid]  = fmaxf(s_red[tid], s_red[tid+s]);
            s_red2[tid] += s_red2[tid+s];
        }
        __syncthreads();
    }
    float tmaxv = s_red[0];
    float cnt   = fmaxf(s_red2[0], 1.f);
    __syncthreads();
    {
        float dt = fmaxf(tmaxv - s_lam[tid], 0.f) * (1.f/86400.f);
        s_lam[tid] = __expf(-0.5f * dt) * s_valid[tid];
    }
    __syncthreads();

    // ---- step 2: pass A — masked mean pool q (DRAM streaming read of WF[b]) ----
    const float4* wf4 = (const float4*)(wf + (size_t)b*Tsz*Dsz);
    {
        int grp = tid >> 6, c4 = tid & 63;
        float4 acc = make_float4(0.f,0.f,0.f,0.f);
        #pragma unroll 8
        for (int t = grp; t < Tsz; t += 8) {
            float4 v = wf4[t*64 + c4];
            float vm = s_valid[t];
            acc.x = fmaf(v.x, vm, acc.x);
            acc.y = fmaf(v.y, vm, acc.y);
            acc.z = fmaf(v.z, vm, acc.z);
            acc.w = fmaf(v.w, vm, acc.w);
        }
        ((float4*)s_acc)[grp*64 + c4] = acc;
    }
    __syncthreads();
    if (tid < Dsz) {
        float s = 0.f;
        #pragma unroll
        for (int g = 0; g < 8; g++) s += s_acc[g*Dsz + tid];
        s_q[tid] = s / cnt;
    }
    __syncthreads();

    // ---- step 3: u = q @ G (G rows broadcast, columns coalesced, L2 hits) ----
    {
        int d = tid & 255, half = tid >> 8;   // half = 0/1 splits the d' range
        const float* Gp = g_G + (size_t)(half*128)*Dsz + d;
        float acc = 0.f;
        #pragma unroll 8
        for (int i = 0; i < 128; i++)
            acc = fmaf(s_q[half*128 + i], Gp[(size_t)i*Dsz], acc);
        s_red[tid] = acc;
    }
    __syncthreads();
    if (tid < Dsz) s_u[tid] = s_red[tid] + s_red[tid + Dsz];
    __syncthreads();

    // ---- step 4: pass B — online decay-softmax weighted pool (WF[b] from L2) ----
    {
        const float4* u4 = (const float4*)s_u;
        float4 ua = u4[lane], ub = u4[lane + 32];

        float m = -3.0e38f, Z = 0.f, S = 0.f;
        float4 ya = make_float4(0.f,0.f,0.f,0.f);
        float4 yb = make_float4(0.f,0.f,0.f,0.f);

        #pragma unroll 4
        for (int t = warp; t < Tsz; t += 16) {
            float4 wa = wf4[t*64 + lane];
            float4 wb = wf4[t*64 + 32 + lane];
            float d = wa.x*ua.x + wa.y*ua.y + wa.z*ua.z + wa.w*ua.w
                    + wb.x*ub.x + wb.y*ub.y + wb.z*ub.z + wb.w*ub.w;
            #pragma unroll
            for (int o = 16; o > 0; o >>= 1) d += __shfl_xor_sync(0xffffffffu, d, o);
            if (s_valid[t] != 0.f) {             // uniform across warp
                float s  = d * 0.0625f;          // 1/sqrt(256)
                float nm = fmaxf(m, s);
                float sc = __expf(m - nm);
                float e  = __expf(s - nm);
                float g  = s_lam[t] * e;
                Z = Z*sc + e;
                S = S*sc + g;
                ya.x = fmaf(ya.x, sc, g*wa.x); ya.y = fmaf(ya.y, sc, g*wa.y);
                ya.z = fmaf(ya.z, sc, g*wa.z); ya.w = fmaf(ya.w, sc, g*wa.w);
                yb.x = fmaf(yb.x, sc, g*wb.x); yb.y = fmaf(yb.y, sc, g*wb.y);
                yb.z = fmaf(yb.z, sc, g*wb.z); yb.w = fmaf(yb.w, sc, g*wb.w);
                m = nm;
            }
        }

        if (lane == 0) s_m[warp] = m;
        __syncthreads();
        float M = s_m[0];
        #pragma unroll
        for (int w = 1; w < 16; w++) M = fmaxf(M, s_m[w]);
        float scw = __expf(m - M);
        if (lane == 0) { s_Z[warp] = Z*scw; s_S[warp] = S*scw; }
        float4* syp4 = (float4*)s_yp;
        syp4[warp*64 + lane]      = make_float4(ya.x*scw, ya.y*scw, ya.z*scw, ya.w*scw);
        syp4[warp*64 + 32 + lane] = make_float4(yb.x*scw, yb.y*scw, yb.z*scw, yb.w*scw);
    }
    __syncthreads();
    if (tid < Dsz) {
        float Zt = 0.f, St = 0.f;
        #pragma unroll
        for (int w = 0; w < 16; w++) { Zt += s_Z[w]; St += s_S[w]; }
        float yv = 0.f;
        #pragma unroll
        for (int w = 0; w < 16; w++) yv += s_yp[w*Dsz + tid];
        float denom = St + 1e-8f*Zt;
        float inv = denom > 0.f ? 1.f/denom : 0.f;
        s_yf[tid] = yv * inv;
    }
    __syncthreads();

    // ---- step 5: L = y @ WV^T (warp-per-row, lane-coalesced, L2 hits) ----
    {
        const float4* yf4 = (const float4*)s_yf;
        float4 yA = yf4[lane*2], yB = yf4[lane*2 + 1];
        #pragma unroll 4
        for (int i = 0; i < 16; i++) {
            int e = warp*16 + i;
            const float4* wr = (const float4*)(WV + (size_t)e*Dsz);
            float4 wA = wr[lane*2], wB = wr[lane*2 + 1];
            float d = wA.x*yA.x + wA.y*yA.y + wA.z*yA.z + wA.w*yA.w
                    + wB.x*yB.x + wB.y*yB.y + wB.z*yB.z + wB.w*yB.w;
            #pragma unroll
            for (int o = 16; o > 0; o >>= 1) d += __shfl_xor_sync(0xffffffffu, d, o);
            if (lane == 0) s_L[e] = d;
        }
    }
    __syncthreads();

    // ---- step 6: epilogue ----
    {
        float r1 = 0.f, r2 = 0.f, L = 0.f, dl = 0.f;
        if (tid < Dsz) {
            L  = s_L[tid];
            dl = L - prevL[(size_t)b*Dsz + tid];
            r1 = dl*dl;
            r2 = fmaf(L, clsw[tid], dl*clsw[Dsz + tid]);
        }
        s_red[tid]  = r1;
        s_red2[tid] = r2;
        __syncthreads();
        for (int s = 256; s > 0; s >>= 1) {
            if (tid < s) { s_red[tid] += s_red[tid+s]; s_red2[tid] += s_red2[tid+s]; }
            __syncthreads();
        }
        size_t te = (size_t)OFF_TE + (size_t)b*513;
        if (tid < Dsz) {
            out[te + tid]        = L;
            out[te + 256 + tid]  = dl;
            out[OFF_L + (size_t)b*Dsz + tid] = L;
        }
        if (tid == 0) {
            float Mt = 0.9f*prevM[b] + 0.1f*sqrtf(s_red[0]);
            out[OFF_M + b] = Mt;
            out[te + 512]  = Mt;
            out[b] = s_red2[0] + Mt*clsw[2*Dsz] + clsb[0];
        }
    }
}

extern "C" void kernel_launch(void* const* d_in, const int* in_sizes, int n_in,
                              void* d_out, int out_size) {
    const float*         wf    = (const float*)d_in[0];
    const float*         ts    = (const float*)d_in[1];
    const float*         prevL = (const float*)d_in[2];
    const float*         prevM = (const float*)d_in[3];
    const unsigned char* pad   = (const unsigned char*)d_in[4];
    const float*         WQ    = (const float*)d_in[5];
    const float*         WK    = (const float*)d_in[6];
    const float*         WV    = (const float*)d_in[7];
    const float*         clsw  = (const float*)d_in[8];
    const float*         clsb  = (const float*)d_in[9];
    float* out = (float*)d_out;

    k_G   <<<Dsz/4, 256>>>(WQ, WK);
    k_main<<<Bsz, 512>>>(wf, ts, pad, WV, prevL, prevM, clsw, clsb, out);
}